// round 10
// baseline (speedup 1.0000x reference)
#include <cuda_runtime.h>
#include <cuda_fp16.h>
#include <cstdint>

#define NN 512
#define DD 128
#define HH 256
#define BB 2

// smem float offsets (main kernel)
#define OFF_HA   0            // [8][256] f32
#define OFF_HB   2048         // [8][256] f32
#define OFF_AS0  4096         // [64][20] b32
#define OFF_AS1  5376         // [64][20] b32
#define OFF_BS0  6656         // [256][20] b32
#define OFF_BS1  11776        // [256][20] b32
#define OFF_B2   16896        // [256]
#define OFF_W3   17152        // [256]
#define OFF_RED  17408        // [64]
#define SMEM_F   17472        // 69888 bytes

#define A_STRIDE_B 5120u      // 1280 words
#define B_STRIDE_B 20480u     // 5120 words

__device__ float  g_hA[BB * NN * HH];
__device__ float  g_hB[BB * NN * HH];
__device__ __half g_W2h[HH * HH];   // W2^T fp16, [n][k] k-contiguous

__device__ __forceinline__ uint32_t smem_u32(const void* p) {
    return (uint32_t)__cvta_generic_to_shared(p);
}
__device__ __forceinline__ void ldmat_x4(uint32_t& r0, uint32_t& r1,
                                         uint32_t& r2, uint32_t& r3, uint32_t a) {
    asm volatile("ldmatrix.sync.aligned.m8n8.x4.shared.b16 {%0,%1,%2,%3}, [%4];"
                 : "=r"(r0), "=r"(r1), "=r"(r2), "=r"(r3) : "r"(a));
}
#define CP_ASYNC16(dst, src) \
    asm volatile("cp.async.cg.shared.global [%0], [%1], 16;" :: "r"(dst), "l"(src))
#define CP_COMMIT() asm volatile("cp.async.commit_group;" ::: "memory")
#define CP_WAIT0()  asm volatile("cp.async.wait_group 0;" ::: "memory")

// ---------------------------------------------------------------------------
// Fused prep: blocks 0..127 -> hA/hB (8 rows each); blocks 128..191 -> W2^T.
// ---------------------------------------------------------------------------
__global__ __launch_bounds__(256) void prep_kernel(
    const float* __restrict__ PhiA, const float* __restrict__ PhiB,
    const float* __restrict__ W1, const float* __restrict__ b1,
    const float* __restrict__ W2) {
    const int t = threadIdx.x;
    if (blockIdx.x >= BB * NN / 8) {
        int base = (blockIdx.x - BB * NN / 8) * 1024 + t * 4;
#pragma unroll
        for (int j = 0; j < 4; j++) {
            int i = base + j;
            int n = i >> 8, k = i & 255;
            g_W2h[i] = __float2half_rn(W2[k * HH + n]);
        }
        return;
    }
    const int bn0 = blockIdx.x * 8;
    const int h = t;
    __shared__ float sAT[DD][8], sBT[DD][8];
#pragma unroll
    for (int j = 0; j < 4; j++) {
        int i = t + j * 256;
        int r = i >> 7, d = i & 127;
        sAT[d][r] = PhiA[(bn0 + r) * DD + d];
        sBT[d][r] = PhiB[(bn0 + r) * DD + d];
    }
    __syncthreads();
    float bias = b1[h];
    float accA[8], accB[8];
#pragma unroll
    for (int r = 0; r < 8; r++) { accA[r] = bias; accB[r] = 0.f; }
#pragma unroll 4
    for (int d = 0; d < DD; d++) {
        float wa = W1[d * HH + h];
        float wb = W1[(DD + d) * HH + h];
        float4 a0 = *(const float4*)&sAT[d][0];
        float4 a1 = *(const float4*)&sAT[d][4];
        float4 b0 = *(const float4*)&sBT[d][0];
        float4 b1v = *(const float4*)&sBT[d][4];
        accA[0] = fmaf(a0.x, wa, accA[0]); accA[1] = fmaf(a0.y, wa, accA[1]);
        accA[2] = fmaf(a0.z, wa, accA[2]); accA[3] = fmaf(a0.w, wa, accA[3]);
        accA[4] = fmaf(a1.x, wa, accA[4]); accA[5] = fmaf(a1.y, wa, accA[5]);
        accA[6] = fmaf(a1.z, wa, accA[6]); accA[7] = fmaf(a1.w, wa, accA[7]);
        accB[0] = fmaf(b0.x, wb, accB[0]); accB[1] = fmaf(b0.y, wb, accB[1]);
        accB[2] = fmaf(b0.z, wb, accB[2]); accB[3] = fmaf(b0.w, wb, accB[3]);
        accB[4] = fmaf(b1v.x, wb, accB[4]); accB[5] = fmaf(b1v.y, wb, accB[5]);
        accB[6] = fmaf(b1v.z, wb, accB[6]); accB[7] = fmaf(b1v.w, wb, accB[7]);
    }
#pragma unroll
    for (int r = 0; r < 8; r++) {
        g_hA[(bn0 + r) * HH + h] = accA[r];
        g_hB[(bn0 + r) * HH + h] = accB[r];
    }
}

// ---------------------------------------------------------------------------
// Pair MLP, fp16 m16n8k16, double-buffered, 2 blocks/SM.
// 256 thr, 8 warps: wm 0..1 (M 32-rows), wn 0..3 (N 64-cols).
// 64 pairs (8 A x 8 B) x 256 cols, K=256 in 8 slabs of 32.
// ---------------------------------------------------------------------------
extern __shared__ float smem[];

__device__ __forceinline__ void build_A_slab(uint32_t* As32, const float* hAs,
                                             const float* hBs, int t, int ks) {
#pragma unroll
    for (int j = 0; j < 2; j++) {
        int i = t + j * 256;             // 0..511 word-pairs
        int m = i >> 3, wp = i & 7;      // m = pair 0..63
        int a = m >> 3, bp = m & 7;
        int kc = ks * 32 + wp * 4;
        float4 va = *(const float4*)&hAs[a * HH + kc];
        float4 vb = *(const float4*)&hBs[bp * HH + kc];
        __half2 h0 = __floats2half2_rn(fmaxf(va.x + vb.x, 0.f),
                                       fmaxf(va.y + vb.y, 0.f));
        __half2 h1 = __floats2half2_rn(fmaxf(va.z + vb.z, 0.f),
                                       fmaxf(va.w + vb.w, 0.f));
        uint2 wv = make_uint2(*(uint32_t*)&h0, *(uint32_t*)&h1);
        *(uint2*)&As32[m * 20 + wp * 2] = wv;
    }
}

__device__ __forceinline__ void issue_B_slab(uint32_t bs_dst, int t, int ks) {
#pragma unroll
    for (int j = 0; j < 4; j++) {
        int i = t + j * 256;             // 0..1023 uint4
        int n = i >> 2, q = i & 3;
        CP_ASYNC16(bs_dst + (uint32_t)(n * 20 + q * 4) * 4,
                   (const char*)g_W2h + ((size_t)n * 128 + ks * 16 + q * 4) * 4);
    }
    CP_COMMIT();
}

__global__ __launch_bounds__(256, 2) void pair_mlp_mma(
    const float* __restrict__ b2, const float* __restrict__ W3,
    const float* __restrict__ b3, float* __restrict__ out) {
    float* hAs = smem + OFF_HA;
    float* hBs = smem + OFF_HB;
    uint32_t* As0 = (uint32_t*)(smem + OFF_AS0);
    uint32_t* As1 = (uint32_t*)(smem + OFF_AS1);
    float* b2s = smem + OFF_B2;
    float* w3s = smem + OFF_W3;
    float* red = smem + OFF_RED;

    const int t    = threadIdx.x;
    const int wid  = t >> 5;
    const int lane = t & 31;
    const int gid  = lane >> 2;
    const int tig  = lane & 3;
    const int wm   = wid & 1;       // M half (32 rows)
    const int wn   = wid >> 1;      // N quarter (64 cols)

    const int bb = blockIdx.z;
    const int n0 = blockIdx.y * 8;
    const int m0 = blockIdx.x * 8;

    const uint32_t as_base = smem_u32((void*)(smem + OFF_AS0));
    const uint32_t bs_base = smem_u32((void*)(smem + OFF_BS0));
    const uint32_t a_l = as_base + ((wm * 32 + (lane & 15)) * 20 + (lane >> 4) * 4) * 4;
    const uint32_t b_l = bs_base + ((wn * 64 + (lane & 15)) * 20 + (lane >> 4) * 4) * 4;

    // B slab 0 fetch rides under the staging LDG latency below
    issue_B_slab(bs_base, t, 0);

    // ---- stage hA (8x256), hB (8x256), b2, W3 ----
#pragma unroll
    for (int j = 0; j < 2; j++) {
        int i = t + j * 256;             // 0..511
        int r = i >> 6, c4 = i & 63;
        ((float4*)hAs)[i] = ((const float4*)(g_hA + (size_t)(bb * NN + n0 + r) * HH))[c4];
        ((float4*)hBs)[i] = ((const float4*)(g_hB + (size_t)(bb * NN + m0 + r) * HH))[c4];
    }
    { b2s[t] = b2[t]; w3s[t] = W3[t]; }
    if (t < 64) red[t] = 0.f;

    float acc[2][8][4];
#pragma unroll
    for (int mt = 0; mt < 2; mt++)
#pragma unroll
        for (int nt = 0; nt < 8; nt++)
#pragma unroll
            for (int c = 0; c < 4; c++) acc[mt][nt][c] = 0.f;

    __syncthreads();            // hAs/hBs ready

    build_A_slab(As0, hAs, hBs, t, 0);
    CP_WAIT0();
    __syncthreads();            // buf0 ready

    for (int ks = 0; ks < 8; ks++) {
        const uint32_t s = (uint32_t)(ks & 1);
        const uint32_t ns = s ^ 1u;

        if (ks < 7) issue_B_slab(bs_base + ns * B_STRIDE_B, t, ks + 1);

        const uint32_t a_ls = a_l + s * A_STRIDE_B;
        const uint32_t b_ls = b_l + s * B_STRIDE_B;
#pragma unroll
        for (int kq = 0; kq < 2; kq++) {
            const uint32_t koff = (uint32_t)(kq * 8 * 4);
            uint32_t afr[2][4];
#pragma unroll
            for (int mt = 0; mt < 2; mt++)
                ldmat_x4(afr[mt][0], afr[mt][1], afr[mt][2], afr[mt][3],
                         a_ls + (uint32_t)(mt * 16 * 20 * 4) + koff);
            uint32_t bfr[8][2];
#pragma unroll
            for (int np = 0; np < 4; np++) {
                uint32_t r0, r1, r2, r3;
                ldmat_x4(r0, r1, r2, r3, b_ls + (uint32_t)(np * 16 * 20 * 4) + koff);
                bfr[np * 2][0] = r0;     bfr[np * 2][1] = r2;
                bfr[np * 2 + 1][0] = r1; bfr[np * 2 + 1][1] = r3;
            }
#pragma unroll
            for (int mt = 0; mt < 2; mt++)
#pragma unroll
                for (int nt = 0; nt < 8; nt++)
                    asm volatile(
                        "mma.sync.aligned.m16n8k16.row.col.f32.f16.f16.f32 "
                        "{%0,%1,%2,%3}, {%4,%5,%6,%7}, {%8,%9}, {%0,%1,%2,%3};"
                        : "+f"(acc[mt][nt][0]), "+f"(acc[mt][nt][1]),
                          "+f"(acc[mt][nt][2]), "+f"(acc[mt][nt][3])
                        : "r"(afr[mt][0]), "r"(afr[mt][1]),
                          "r"(afr[mt][2]), "r"(afr[mt][3]),
                          "r"(bfr[nt][0]), "r"(bfr[nt][1]));
        }

        if (ks < 7) {
            build_A_slab(s ? As0 : As1, hAs, hBs, t, ks + 1);
            CP_WAIT0();
        }
        __syncthreads();
    }

    // ---- epilogue: relu(acc+b2) . W3, reduce ----
    float psum[2][2] = {{0.f, 0.f}, {0.f, 0.f}};
#pragma unroll
    for (int mt = 0; mt < 2; mt++)
#pragma unroll
        for (int nt = 0; nt < 8; nt++) {
            int col = wn * 64 + nt * 8 + tig * 2;
            float bq0 = b2s[col], bq1 = b2s[col + 1];
            float wq0 = w3s[col], wq1 = w3s[col + 1];
            psum[mt][0] = fmaf(fmaxf(acc[mt][nt][0] + bq0, 0.f), wq0, psum[mt][0]);
            psum[mt][0] = fmaf(fmaxf(acc[mt][nt][1] + bq1, 0.f), wq1, psum[mt][0]);
            psum[mt][1] = fmaf(fmaxf(acc[mt][nt][2] + bq0, 0.f), wq0, psum[mt][1]);
            psum[mt][1] = fmaf(fmaxf(acc[mt][nt][3] + bq1, 0.f), wq1, psum[mt][1]);
        }

#pragma unroll
    for (int off = 1; off <= 2; off <<= 1)
#pragma unroll
        for (int mt = 0; mt < 2; mt++)
#pragma unroll
            for (int hi = 0; hi < 2; hi++)
                psum[mt][hi] += __shfl_xor_sync(0xffffffffu, psum[mt][hi], off);

    if (tig == 0) {
#pragma unroll
        for (int mt = 0; mt < 2; mt++)
#pragma unroll
            for (int hi = 0; hi < 2; hi++)
                atomicAdd(&red[wm * 32 + mt * 16 + hi * 8 + gid], psum[mt][hi]);
    }
    __syncthreads();
    if (t < 64) {
        int a = t >> 3, bp = t & 7;
        out[(size_t)(bb * NN + n0 + a) * NN + (m0 + bp)] = red[t] + b3[0];
    }
}

// ---------------------------------------------------------------------------
extern "C" void kernel_launch(void* const* d_in, const int* in_sizes, int n_in,
                              void* d_out, int out_size) {
    const float* PhiA = (const float*)d_in[0];
    const float* PhiB = (const float*)d_in[1];
    const float* W1   = (const float*)d_in[2];
    const float* b1   = (const float*)d_in[3];
    const float* W2   = (const float*)d_in[4];
    const float* b2   = (const float*)d_in[5];
    const float* W3   = (const float*)d_in[6];
    const float* b3   = (const float*)d_in[7];
    float* out = (float*)d_out;

    prep_kernel<<<BB * NN / 8 + 64, 256>>>(PhiA, PhiB, W1, b1, W2);

    const int smem_bytes = SMEM_F * 4;   // 69888
    cudaFuncSetAttribute(pair_mlp_mma,
                         cudaFuncAttributeMaxDynamicSharedMemorySize, smem_bytes);
    dim3 grid(NN / 8, NN / 8, BB);   // 64 x 64 x 2 = 8192
    pair_mlp_mma<<<grid, 256, smem_bytes>>>(b2, W3, b3, out);
}

// round 11
// speedup vs baseline: 1.2253x; 1.2253x over previous
#include <cuda_runtime.h>
#include <cuda_fp16.h>
#include <cstdint>

#define NN 512
#define DD 128
#define HH 256
#define BB 2

// smem float offsets (main kernel)
#define OFF_HA   0            // [16][256] f32
#define OFF_HB   4096         // [8][256]  f32
#define OFF_A    6144         // [128][132] b32 words (full-K A image, fp16x2)
#define OFF_BS0  23040        // [256][20] b32
#define OFF_BS1  28160        // [256][20] b32
#define OFF_B2   33280        // [256]
#define OFF_W3   33536        // [256]
#define OFF_RED  33792        // [128]
#define SMEM_F   33920        // 135680 bytes

#define A_ROW_W  132u         // words per A row (128 data + 4 pad)
#define B_STRIDE_B 20480u     // bytes between B buffers

__device__ float  g_hA[BB * NN * HH];
__device__ float  g_hB[BB * NN * HH];
__device__ __half g_W2h[HH * HH];   // W2^T fp16, [n][k] k-contiguous

__device__ __forceinline__ uint32_t smem_u32(const void* p) {
    return (uint32_t)__cvta_generic_to_shared(p);
}
__device__ __forceinline__ void ldmat_x4(uint32_t& r0, uint32_t& r1,
                                         uint32_t& r2, uint32_t& r3, uint32_t a) {
    asm volatile("ldmatrix.sync.aligned.m8n8.x4.shared.b16 {%0,%1,%2,%3}, [%4];"
                 : "=r"(r0), "=r"(r1), "=r"(r2), "=r"(r3) : "r"(a));
}
#define CP_ASYNC16(dst, src) \
    asm volatile("cp.async.cg.shared.global [%0], [%1], 16;" :: "r"(dst), "l"(src))
#define CP_COMMIT() asm volatile("cp.async.commit_group;" ::: "memory")
#define CP_WAIT0()  asm volatile("cp.async.wait_group 0;" ::: "memory")

// ---------------------------------------------------------------------------
// Fused prep: blocks 0..127 -> hA/hB (8 rows each); blocks 128..191 -> W2^T.
// ---------------------------------------------------------------------------
__global__ __launch_bounds__(256) void prep_kernel(
    const float* __restrict__ PhiA, const float* __restrict__ PhiB,
    const float* __restrict__ W1, const float* __restrict__ b1,
    const float* __restrict__ W2) {
    const int t = threadIdx.x;
    if (blockIdx.x >= BB * NN / 8) {
        int base = (blockIdx.x - BB * NN / 8) * 1024 + t * 4;
#pragma unroll
        for (int j = 0; j < 4; j++) {
            int i = base + j;
            int n = i >> 8, k = i & 255;
            g_W2h[i] = __float2half_rn(W2[k * HH + n]);
        }
        return;
    }
    const int bn0 = blockIdx.x * 8;
    const int h = t;
    __shared__ float sAT[DD][8], sBT[DD][8];
#pragma unroll
    for (int j = 0; j < 4; j++) {
        int i = t + j * 256;
        int r = i >> 7, d = i & 127;
        sAT[d][r] = PhiA[(bn0 + r) * DD + d];
        sBT[d][r] = PhiB[(bn0 + r) * DD + d];
    }
    __syncthreads();
    float bias = b1[h];
    float accA[8], accB[8];
#pragma unroll
    for (int r = 0; r < 8; r++) { accA[r] = bias; accB[r] = 0.f; }
#pragma unroll 4
    for (int d = 0; d < DD; d++) {
        float wa = W1[d * HH + h];
        float wb = W1[(DD + d) * HH + h];
        float4 a0 = *(const float4*)&sAT[d][0];
        float4 a1 = *(const float4*)&sAT[d][4];
        float4 b0 = *(const float4*)&sBT[d][0];
        float4 b1v = *(const float4*)&sBT[d][4];
        accA[0] = fmaf(a0.x, wa, accA[0]); accA[1] = fmaf(a0.y, wa, accA[1]);
        accA[2] = fmaf(a0.z, wa, accA[2]); accA[3] = fmaf(a0.w, wa, accA[3]);
        accA[4] = fmaf(a1.x, wa, accA[4]); accA[5] = fmaf(a1.y, wa, accA[5]);
        accA[6] = fmaf(a1.z, wa, accA[6]); accA[7] = fmaf(a1.w, wa, accA[7]);
        accB[0] = fmaf(b0.x, wb, accB[0]); accB[1] = fmaf(b0.y, wb, accB[1]);
        accB[2] = fmaf(b0.z, wb, accB[2]); accB[3] = fmaf(b0.w, wb, accB[3]);
        accB[4] = fmaf(b1v.x, wb, accB[4]); accB[5] = fmaf(b1v.y, wb, accB[5]);
        accB[6] = fmaf(b1v.z, wb, accB[6]); accB[7] = fmaf(b1v.w, wb, accB[7]);
    }
#pragma unroll
    for (int r = 0; r < 8; r++) {
        g_hA[(bn0 + r) * HH + h] = accA[r];
        g_hB[(bn0 + r) * HH + h] = accB[r];
    }
}

// ---------------------------------------------------------------------------
// Pair MLP, fp16 m16n8k16. A image built ONCE; lean MMA loop over B slabs.
// 512 thr, 16 warps: wm 0..3 (M 32-rows), wn 0..3 (N 64-cols).
// 128 pairs (16 A x 8 B) x 256 cols, K=256 (8 B-slabs of 32).
// ---------------------------------------------------------------------------
extern __shared__ float smem[];

__device__ __forceinline__ void issue_B_slab(uint32_t bs_dst, int t, int ks) {
#pragma unroll
    for (int j = 0; j < 2; j++) {
        int i = t + j * 512;             // 0..1023 uint4
        int n = i >> 2, q = i & 3;
        CP_ASYNC16(bs_dst + (uint32_t)(n * 20 + q * 4) * 4,
                   (const char*)g_W2h + ((size_t)n * 128 + ks * 16 + q * 4) * 4);
    }
    CP_COMMIT();
}

__global__ __launch_bounds__(512, 1) void pair_mlp_mma(
    const float* __restrict__ b2, const float* __restrict__ W3,
    const float* __restrict__ b3, float* __restrict__ out) {
    float* hAs = smem + OFF_HA;
    float* hBs = smem + OFF_HB;
    uint32_t* A32 = (uint32_t*)(smem + OFF_A);
    float* b2s = smem + OFF_B2;
    float* w3s = smem + OFF_W3;
    float* red = smem + OFF_RED;

    const int t    = threadIdx.x;
    const int wid  = t >> 5;
    const int lane = t & 31;
    const int gid  = lane >> 2;
    const int tig  = lane & 3;
    const int wm   = wid & 3;       // M quadrant (32 rows)
    const int wn   = wid >> 2;      // N quarter (64 cols)

    const int bb = blockIdx.z;
    const int n0 = blockIdx.y * 16;
    const int m0 = blockIdx.x * 8;

    const uint32_t as_base = smem_u32((void*)(smem + OFF_A));
    const uint32_t bs_base = smem_u32((void*)(smem + OFF_BS0));
    const uint32_t a_l = as_base + ((wm * 32 + (lane & 15)) * A_ROW_W + (lane >> 4) * 4) * 4;
    const uint32_t b_l = bs_base + ((wn * 64 + (lane & 15)) * 20 + (lane >> 4) * 4) * 4;

    // B slab 0 rides under the staging loads below
    issue_B_slab(bs_base, t, 0);

    // ---- stage hA (16x256), hB (8x256), b2, W3 ----
#pragma unroll
    for (int j = 0; j < 2; j++) {
        int i = t + j * 512;
        int r = i >> 6, c4 = i & 63;
        ((float4*)hAs)[i] = ((const float4*)(g_hA + (size_t)(bb * NN + n0 + r) * HH))[c4];
        if (i < 512)
            ((float4*)hBs)[i] = ((const float4*)(g_hB + (size_t)(bb * NN + m0 + (i >> 6)) * HH))[c4];
    }
    if (t < 256) { b2s[t] = b2[t]; w3s[t] = W3[t]; }
    if (t < 128) red[t] = 0.f;

    float acc[2][8][4];
#pragma unroll
    for (int mt = 0; mt < 2; mt++)
#pragma unroll
        for (int nt = 0; nt < 8; nt++)
#pragma unroll
            for (int c = 0; c < 4; c++) acc[mt][nt][c] = 0.f;

    __syncthreads();            // hAs/hBs ready

    // ---- build FULL A image once: relu(hA+hB) -> fp16x2, [128][132] words ----
#pragma unroll
    for (int j = 0; j < 16; j++) {
        int i = t + j * 512;             // 0..8191 uint2 (4 k each)
        int m = i >> 6, wp = i & 63;
        int a = m >> 3, bp = m & 7;
        int kc = wp * 4;
        float4 va = *(const float4*)&hAs[a * HH + kc];
        float4 vb = *(const float4*)&hBs[bp * HH + kc];
        __half2 h0 = __floats2half2_rn(fmaxf(va.x + vb.x, 0.f),
                                       fmaxf(va.y + vb.y, 0.f));
        __half2 h1 = __floats2half2_rn(fmaxf(va.z + vb.z, 0.f),
                                       fmaxf(va.w + vb.w, 0.f));
        uint2 wv = make_uint2(*(uint32_t*)&h0, *(uint32_t*)&h1);
        *(uint2*)&A32[m * A_ROW_W + wp * 2] = wv;
    }
    CP_WAIT0();
    __syncthreads();            // A image + B slab 0 ready

    for (int ks = 0; ks < 8; ks++) {
        const uint32_t s = (uint32_t)(ks & 1);
        const uint32_t ns = s ^ 1u;

        if (ks < 7) issue_B_slab(bs_base + ns * B_STRIDE_B, t, ks + 1);

        const uint32_t b_ls = b_l + s * B_STRIDE_B;
#pragma unroll
        for (int kq = 0; kq < 2; kq++) {
            // A fragment: k-chunk index (ks*2+kq), 8 words per chunk in row
            const uint32_t akoff = (uint32_t)((ks * 2 + kq) * 8 * 4);
            const uint32_t bkoff = (uint32_t)(kq * 8 * 4);
            uint32_t afr[2][4];
#pragma unroll
            for (int mt = 0; mt < 2; mt++)
                ldmat_x4(afr[mt][0], afr[mt][1], afr[mt][2], afr[mt][3],
                         a_l + (uint32_t)(mt * 16 * A_ROW_W * 4) + akoff);
            uint32_t bfr[8][2];
#pragma unroll
            for (int np = 0; np < 4; np++) {
                uint32_t r0, r1, r2, r3;
                ldmat_x4(r0, r1, r2, r3, b_ls + (uint32_t)(np * 16 * 20 * 4) + bkoff);
                bfr[np * 2][0] = r0;     bfr[np * 2][1] = r2;
                bfr[np * 2 + 1][0] = r1; bfr[np * 2 + 1][1] = r3;
            }
#pragma unroll
            for (int mt = 0; mt < 2; mt++)
#pragma unroll
                for (int nt = 0; nt < 8; nt++)
                    asm volatile(
                        "mma.sync.aligned.m16n8k16.row.col.f32.f16.f16.f32 "
                        "{%0,%1,%2,%3}, {%4,%5,%6,%7}, {%8,%9}, {%0,%1,%2,%3};"
                        : "+f"(acc[mt][nt][0]), "+f"(acc[mt][nt][1]),
                          "+f"(acc[mt][nt][2]), "+f"(acc[mt][nt][3])
                        : "r"(afr[mt][0]), "r"(afr[mt][1]),
                          "r"(afr[mt][2]), "r"(afr[mt][3]),
                          "r"(bfr[nt][0]), "r"(bfr[nt][1]));
        }

        if (ks < 7) CP_WAIT0();
        __syncthreads();
    }

    // ---- epilogue: relu(acc+b2) . W3, reduce ----
    float psum[2][2] = {{0.f, 0.f}, {0.f, 0.f}};
#pragma unroll
    for (int mt = 0; mt < 2; mt++)
#pragma unroll
        for (int nt = 0; nt < 8; nt++) {
            int col = wn * 64 + nt * 8 + tig * 2;
            float bq0 = b2s[col], bq1 = b2s[col + 1];
            float wq0 = w3s[col], wq1 = w3s[col + 1];
            psum[mt][0] = fmaf(fmaxf(acc[mt][nt][0] + bq0, 0.f), wq0, psum[mt][0]);
            psum[mt][0] = fmaf(fmaxf(acc[mt][nt][1] + bq1, 0.f), wq1, psum[mt][0]);
            psum[mt][1] = fmaf(fmaxf(acc[mt][nt][2] + bq0, 0.f), wq0, psum[mt][1]);
            psum[mt][1] = fmaf(fmaxf(acc[mt][nt][3] + bq1, 0.f), wq1, psum[mt][1]);
        }

#pragma unroll
    for (int off = 1; off <= 2; off <<= 1)
#pragma unroll
        for (int mt = 0; mt < 2; mt++)
#pragma unroll
            for (int hi = 0; hi < 2; hi++)
                psum[mt][hi] += __shfl_xor_sync(0xffffffffu, psum[mt][hi], off);

    if (tig == 0) {
#pragma unroll
        for (int mt = 0; mt < 2; mt++)
#pragma unroll
            for (int hi = 0; hi < 2; hi++)
                atomicAdd(&red[wm * 32 + mt * 16 + hi * 8 + gid], psum[mt][hi]);
    }
    __syncthreads();
    if (t < 128) {
        int a = t >> 3, bp = t & 7;
        out[(size_t)(bb * NN + n0 + a) * NN + (m0 + bp)] = red[t] + b3[0];
    }
}

// ---------------------------------------------------------------------------
extern "C" void kernel_launch(void* const* d_in, const int* in_sizes, int n_in,
                              void* d_out, int out_size) {
    const float* PhiA = (const float*)d_in[0];
    const float* PhiB = (const float*)d_in[1];
    const float* W1   = (const float*)d_in[2];
    const float* b1   = (const float*)d_in[3];
    const float* W2   = (const float*)d_in[4];
    const float* b2   = (const float*)d_in[5];
    const float* W3   = (const float*)d_in[6];
    const float* b3   = (const float*)d_in[7];
    float* out = (float*)d_out;

    prep_kernel<<<BB * NN / 8 + 64, 256>>>(PhiA, PhiB, W1, b1, W2);

    const int smem_bytes = SMEM_F * 4;   // 135680
    cudaFuncSetAttribute(pair_mlp_mma,
                         cudaFuncAttributeMaxDynamicSharedMemorySize, smem_bytes);
    dim3 grid(NN / 8, NN / 16, BB);   // 64 x 32 x 2 = 4096
    pair_mlp_mma<<<grid, 512, smem_bytes>>>(b2, W3, b3, out);
}